// round 1
// baseline (speedup 1.0000x reference)
#include <cuda_runtime.h>

// Problem constants
#define BB   4
#define HH   80
#define WW   80
#define CH   256
#define NC   22
#define DIM  256
#define P    (BB*HH*WW)      // 25600 pixels
#define KW   (9*DIM)         // 2304: stride per input channel in conv_w

// GEMM tiling
#define TM   64
#define TN   128
#define KC   32

// Scratch: norm-scaled selection weights, sel'[p][k] = norm[p]*sel[p][k]
__device__ float g_seln[P * 9];

// ---------------------------------------------------------------------------
// Kernel 1: per-pixel selection weights + normalization
// sel[k] = sum over classes c where seg_center[c]==max of seg_neighbor_k[c]
// (exactly 0 for out-of-bounds neighbors); norm = cnt>0 ? 9/cnt : 0
// ---------------------------------------------------------------------------
__global__ void selnorm_kernel(const float* __restrict__ seg)
{
    int p = blockIdx.x * blockDim.x + threadIdx.x;
    if (p >= P) return;
    int w = p % WW;
    int h = (p / WW) % HH;

    const float* c0 = seg + (size_t)p * NC;
    float cv[NC];
#pragma unroll
    for (int c = 0; c < NC; c++) cv[c] = c0[c];

    float smax = cv[0];
#pragma unroll
    for (int c = 1; c < NC; c++) smax = fmaxf(smax, cv[c]);

    float sel[9];
    int cnt = 0;
#pragma unroll
    for (int k = 0; k < 9; k++) {
        int dh = k / 3 - 1, dw = k % 3 - 1;
        int hh = h + dh, ww = w + dw;
        float s = 0.0f;
        if (hh >= 0 && hh < HH && ww >= 0 && ww < WW) {
            const float* nb = seg + (size_t)(p + dh * WW + dw) * NC;
#pragma unroll
            for (int c = 0; c < NC; c++)
                if (cv[c] == smax) s += nb[c];
        }
        sel[k] = s;
        if (s != 0.0f) cnt++;
    }
    float nrm = (cnt > 0) ? 9.0f / (float)cnt : 0.0f;
#pragma unroll
    for (int k = 0; k < 9; k++) g_seln[p * 9 + k] = sel[k] * nrm;
}

// ---------------------------------------------------------------------------
// Packed f32x2 FMA (Blackwell FFMA2; only reachable via PTX)
// ---------------------------------------------------------------------------
__device__ __forceinline__ void ffma2(float2& d, float2 a, float2 b)
{
    unsigned long long& dd = reinterpret_cast<unsigned long long&>(d);
    unsigned long long aa, bb;
    aa = reinterpret_cast<unsigned long long&>(a);
    bb = reinterpret_cast<unsigned long long&>(b);
    asm("fma.rn.f32x2 %0, %1, %2, %0;" : "+l"(dd) : "l"(aa), "l"(bb));
}

// ---------------------------------------------------------------------------
// Kernel 2: implicit GEMM
// out[p,d] = sum_{k,c} (seln[p,k]*x[nb(p,k),c]) * w[c,k,d]
// M = 25600 (pixels), N = 256 (DIM), K = 9 taps x 256 channels
// Block: TM=64 x TN=128, 256 threads, each thread 4M x 8N (as 4x4 float2).
// ---------------------------------------------------------------------------
__global__ __launch_bounds__(256) void pconv_gemm(
    const float* __restrict__ x,
    const float* __restrict__ wgt,
    float* __restrict__ out)
{
    __shared__ float As[KC][TM];   // [channel][pixel]
    __shared__ float Bs[KC][TN];   // [channel][d]

    int tid = threadIdx.x;
    int p0  = blockIdx.x * TM;
    int d0  = blockIdx.y * TN;

    // compute-phase coordinates: 16x16 thread grid
    int ty = tid >> 4;        // M rows ty*4 .. ty*4+3
    int tx = tid & 15;        // N cols tx*8 .. tx*8+7

    // A-loader coordinates: 64 pixels x 4 channel groups
    int ai = tid & 63;        // pixel within tile
    int ac = (tid >> 6) << 2; // channel base {0,4,8,12}; +16 for 2nd pass

    // B-loader coordinates: 8 row groups x 32 col groups
    int br = tid >> 5;        // 0..7
    int bc = (tid & 31) << 2; // col*4

    // pixel geometry (for the A loader's lane)
    int p = p0 + ai;

    float2 acc[4][4];
#pragma unroll
    for (int i = 0; i < 4; i++)
#pragma unroll
        for (int j = 0; j < 4; j++) acc[i][j] = make_float2(0.0f, 0.0f);

#pragma unroll 1
    for (int k = 0; k < 9; k++) {
        int dh = k / 3 - 1, dw = k % 3 - 1;
        // sel==0 for OOB neighbors, so just clamp the flat index into valid mem
        int nb = p + dh * WW + dw;
        nb = nb < 0 ? 0 : (nb >= P ? P - 1 : nb);
        const float* xrow = x + (size_t)nb * CH;
        float selk = g_seln[p * 9 + k];
        const float* wbase = wgt + (size_t)k * DIM + d0;

#pragma unroll 1
        for (int ct = 0; ct < CH; ct += KC) {
            // ---- global -> registers ----
            float4 a0 = *(const float4*)(xrow + ct + ac);
            float4 a1 = *(const float4*)(xrow + ct + ac + 16);
            float4 bld[4];
#pragma unroll
            for (int s = 0; s < 4; s++) {
                int r = br + s * 8;
                bld[s] = *(const float4*)(wbase + (size_t)(ct + r) * KW + bc);
            }

            __syncthreads();   // previous compute done reading smem
            // ---- registers -> shared (A scaled by sel) ----
            As[ac + 0][ai]  = a0.x * selk;
            As[ac + 1][ai]  = a0.y * selk;
            As[ac + 2][ai]  = a0.z * selk;
            As[ac + 3][ai]  = a0.w * selk;
            As[ac + 16][ai] = a1.x * selk;
            As[ac + 17][ai] = a1.y * selk;
            As[ac + 18][ai] = a1.z * selk;
            As[ac + 19][ai] = a1.w * selk;
#pragma unroll
            for (int s = 0; s < 4; s++)
                *(float4*)&Bs[br + s * 8][bc] = bld[s];
            __syncthreads();

            // ---- compute ----
#pragma unroll
            for (int cc = 0; cc < KC; cc++) {
                float4 av = *(const float4*)&As[cc][ty * 4];
                float4 b0 = *(const float4*)&Bs[cc][tx * 8];
                float4 b1 = *(const float4*)&Bs[cc][tx * 8 + 4];
                float2 bp[4];
                bp[0] = make_float2(b0.x, b0.y);
                bp[1] = make_float2(b0.z, b0.w);
                bp[2] = make_float2(b1.x, b1.y);
                bp[3] = make_float2(b1.z, b1.w);
                float am[4] = {av.x, av.y, av.z, av.w};
#pragma unroll
                for (int i = 0; i < 4; i++) {
                    float2 aa = make_float2(am[i], am[i]);
#pragma unroll
                    for (int j = 0; j < 4; j++) ffma2(acc[i][j], aa, bp[j]);
                }
            }
        }
    }

    // ---- epilogue ----
#pragma unroll
    for (int i = 0; i < 4; i++) {
        float2* orow = (float2*)(out + (size_t)(p0 + ty * 4 + i) * DIM + d0 + tx * 8);
#pragma unroll
        for (int j = 0; j < 4; j++) orow[j] = acc[i][j];
    }
}

// ---------------------------------------------------------------------------
extern "C" void kernel_launch(void* const* d_in, const int* in_sizes, int n_in,
                              void* d_out, int out_size)
{
    const float* x   = (const float*)d_in[0];
    const float* seg = (const float*)d_in[1];
    const float* wgt = (const float*)d_in[2];
    float* out = (float*)d_out;

    selnorm_kernel<<<P / 256, 256>>>(seg);

    dim3 grid(P / TM, DIM / TN);
    pconv_gemm<<<grid, 256>>>(x, wgt, out);
}

// round 3
// speedup vs baseline: 3.5275x; 3.5275x over previous
#include <cuda_runtime.h>
#include <cuda_bf16.h>
#include <cstdint>

// ---------------------------------------------------------------- constants
#define HH 80
#define WW 80
#define CH 256
#define NC 22
#define DIM 256
#define P 25600              // 4*80*80 pixels
#define NCHUNK 36            // 9 taps * 4 chunks of 64 channels
#define STAGE 65536          // bytes per pipeline stage
// stage layout: A_hi[16K] A_lo[16K] B_hi[16K] B_lo[16K]

// device scratch
__device__ float g_seln[P * 9];
__device__ uint4 g_bh[72 * 1024];   // [chunk*2+nblk] 16KB blocks, smem-image (swizzled)
__device__ uint4 g_bl[72 * 1024];

// ---------------------------------------------------------------- helpers
static __device__ __forceinline__ uint32_t smem_u32(const void* p) {
    uint32_t a;
    asm("{ .reg .u64 t; cvta.to.shared.u64 t, %1; cvt.u32.u64 %0, t; }" : "=r"(a) : "l"(p));
    return a;
}

#define LDSM4(r, addr) \
    asm volatile("ldmatrix.sync.aligned.m8n8.x4.shared.b16 {%0,%1,%2,%3},[%4];" \
        : "=r"((r)[0]), "=r"((r)[1]), "=r"((r)[2]), "=r"((r)[3]) : "r"(addr))
#define LDSM2(r, addr) \
    asm volatile("ldmatrix.sync.aligned.m8n8.x2.shared.b16 {%0,%1},[%2];" \
        : "=r"((r)[0]), "=r"((r)[1]) : "r"(addr))
#define MMA(acc, a, b) \
    asm volatile("mma.sync.aligned.m16n8k16.row.col.f32.bf16.bf16.f32 " \
        "{%0,%1,%2,%3},{%4,%5,%6,%7},{%8,%9},{%0,%1,%2,%3};" \
        : "+f"((acc)[0]), "+f"((acc)[1]), "+f"((acc)[2]), "+f"((acc)[3]) \
        : "r"((a)[0]), "r"((a)[1]), "r"((a)[2]), "r"((a)[3]), "r"((b)[0]), "r"((b)[1]))
#define CPA(dst, src) \
    asm volatile("cp.async.cg.shared.global [%0], [%1], 16;" :: "r"(dst), "l"(src))

// split 8 floats into packed bf16 hi/lo pairs
static __device__ __forceinline__ void split8(const float* v, uint32_t* h4, uint32_t* l4) {
#pragma unroll
    for (int j = 0; j < 4; j++) {
        unsigned short h0 = __bfloat16_as_ushort(__float2bfloat16(v[2*j]));
        unsigned short h1 = __bfloat16_as_ushort(__float2bfloat16(v[2*j+1]));
        float f0 = __uint_as_float((uint32_t)h0 << 16);
        float f1 = __uint_as_float((uint32_t)h1 << 16);
        unsigned short l0 = __bfloat16_as_ushort(__float2bfloat16(v[2*j]   - f0));
        unsigned short l1 = __bfloat16_as_ushort(__float2bfloat16(v[2*j+1] - f1));
        h4[j] = (uint32_t)h0 | ((uint32_t)h1 << 16);
        l4[j] = (uint32_t)l0 | ((uint32_t)l1 << 16);
    }
}

// ---------------------------------------------------------------- kernel 1: selection weights
__global__ void selnorm_kernel(const float* __restrict__ seg)
{
    int p = blockIdx.x * blockDim.x + threadIdx.x;
    if (p >= P) return;
    int w = p % WW;
    int h = (p / WW) % HH;

    const float* c0 = seg + (size_t)p * NC;
    float cv[NC];
#pragma unroll
    for (int c = 0; c < NC; c++) cv[c] = c0[c];
    float smax = cv[0];
#pragma unroll
    for (int c = 1; c < NC; c++) smax = fmaxf(smax, cv[c]);

    float sel[9];
    int cnt = 0;
#pragma unroll
    for (int k = 0; k < 9; k++) {
        int dh = k / 3 - 1, dw = k % 3 - 1;
        int hh = h + dh, ww = w + dw;
        float s = 0.0f;
        if (hh >= 0 && hh < HH && ww >= 0 && ww < WW) {
            const float* nb = seg + (size_t)(p + dh * WW + dw) * NC;
#pragma unroll
            for (int c = 0; c < NC; c++)
                if (cv[c] == smax) s += nb[c];
        }
        sel[k] = s;
        if (s != 0.0f) cnt++;
    }
    float nrm = (cnt > 0) ? 9.0f / (float)cnt : 0.0f;
#pragma unroll
    for (int k = 0; k < 9; k++) g_seln[p * 9 + k] = sel[k] * nrm;
}

// ---------------------------------------------------------------- kernel 2: weight prep
// conv_w[c][tap][d] -> per (chunk, nblk) 16KB block: rows = d_local (128),
// cols = channel-within-chunk (64), bf16 hi/lo, SW128 swizzle baked in.
__global__ void prep_b(const float* __restrict__ wgt)
{
    int id = blockIdx.x * blockDim.x + threadIdx.x;   // 73728 threads
    int cc8  = id & 7;
    int row  = (id >> 3) & 127;
    int blk  = id >> 10;           // 0..71
    int nblk = blk & 1;
    int chunk = blk >> 1;
    int ktap = chunk >> 2, ct = chunk & 3;
    int d  = nblk * 128 + row;
    int c0 = ct * 64 + cc8 * 8;

    float v[8];
#pragma unroll
    for (int j = 0; j < 8; j++)
        v[j] = wgt[(size_t)(c0 + j) * (9 * DIM) + ktap * DIM + d];

    uint32_t h4[4], l4[4];
    split8(v, h4, l4);

    int idx = blk * 1024 + row * 8 + (cc8 ^ (row & 7));
    g_bh[idx] = make_uint4(h4[0], h4[1], h4[2], h4[3]);
    g_bl[idx] = make_uint4(l4[0], l4[1], l4[2], l4[3]);
}

// ---------------------------------------------------------------- kernel 3: HMMA implicit GEMM
// CTA: 128(M pixels) x 128(N dims), 512 threads = 16 warps (4M x 4N), warp 32x32.
__global__ __launch_bounds__(512, 1) void pconv_mma(
    const float* __restrict__ x, float* __restrict__ out)
{
    extern __shared__ __align__(1024) char smem[];
    const uint32_t sb = smem_u32(smem);
    const int tid = threadIdx.x, wid = tid >> 5, lid = tid & 31;
    const int p0 = blockIdx.x * 128;
    const int nblk = blockIdx.y;
    const int wm = wid & 3, wn = wid >> 2;

    // A-fill mapping: thread -> (row 0..127, quarter 0..3 of 64 channels)
    const int frow = tid >> 2, fq = tid & 3;
    const int fp = p0 + frow;

    float4 areg[4];
    float aselk = 0.0f;

    float acc[2][4][4];
#pragma unroll
    for (int i = 0; i < 2; i++)
#pragma unroll
        for (int j = 0; j < 4; j++)
#pragma unroll
            for (int r = 0; r < 4; r++) acc[i][j][r] = 0.0f;

    // ldmatrix lane addressing (SW128 swizzle: chunk ^= row&7, rows are 128B)
    const int arow = wm * 32 + (lid & 15);
    const int asw  = arow & 7;
    const int achp = lid >> 4;
    const int brow = wn * 32 + (lid & 7);
    const int bsw  = brow & 7;
    const int bchp = (lid >> 3) & 1;

    auto issueA = [&](int chunk) {
        int ktap = chunk >> 2, ct = chunk & 3;
        int dh = ktap / 3 - 1, dw = ktap % 3 - 1;
        int nb = fp + dh * WW + dw;                 // sel==0 for OOB: clamp only
        nb = nb < 0 ? 0 : (nb >= P ? P - 1 : nb);
        const float4* src = (const float4*)(x + (size_t)nb * CH + ct * 64 + fq * 16);
        areg[0] = src[0]; areg[1] = src[1]; areg[2] = src[2]; areg[3] = src[3];
        aselk = g_seln[fp * 9 + ktap];
    };
    auto storeA = [&](char* st) {
        char* Ah = st;
        char* Al = st + 16384;
#pragma unroll
        for (int half = 0; half < 2; half++) {
            float4 u0 = areg[half * 2], u1 = areg[half * 2 + 1];
            float v[8] = { u0.x * aselk, u0.y * aselk, u0.z * aselk, u0.w * aselk,
                           u1.x * aselk, u1.y * aselk, u1.z * aselk, u1.w * aselk };
            uint32_t h4[4], l4[4];
            split8(v, h4, l4);
            int off = frow * 128 + (((fq * 2 + half) ^ (frow & 7)) << 4);
            *(uint4*)(Ah + off) = make_uint4(h4[0], h4[1], h4[2], h4[3]);
            *(uint4*)(Al + off) = make_uint4(l4[0], l4[1], l4[2], l4[3]);
        }
    };
    auto issueB = [&](int chunk, uint32_t stu) {
        const uint4* sh = g_bh + (size_t)(chunk * 2 + nblk) * 1024;
        const uint4* sl = g_bl + (size_t)(chunk * 2 + nblk) * 1024;
        uint32_t Bh = stu + 32768, Bl = stu + 49152;
        CPA(Bh + tid * 16,         sh + tid);
        CPA(Bh + (tid + 512) * 16, sh + tid + 512);
        CPA(Bl + tid * 16,         sl + tid);
        CPA(Bl + (tid + 512) * 16, sl + tid + 512);
        asm volatile("cp.async.commit_group;" ::: "memory");
    };
    auto compute = [&](uint32_t stu) {
        uint32_t Ah = stu, Al = stu + 16384, Bh = stu + 32768, Bl = stu + 49152;
#pragma unroll
        for (int ks = 0; ks < 4; ks++) {
            uint32_t ah[2][4], al[2][4], bh[4][2], bl[4][2];
#pragma unroll
            for (int mt = 0; mt < 2; mt++) {
                uint32_t off = (uint32_t)(arow + mt * 16) * 128
                             + (((ks * 2 + achp) ^ asw) << 4);
                LDSM4(ah[mt], Ah + off);
                LDSM4(al[mt], Al + off);
            }
#pragma unroll
            for (int nt = 0; nt < 4; nt++) {
                uint32_t off = (uint32_t)(brow + nt * 8) * 128
                             + (((ks * 2 + bchp) ^ bsw) << 4);
                LDSM2(bh[nt], Bh + off);
                LDSM2(bl[nt], Bl + off);
            }
#pragma unroll
            for (int mt = 0; mt < 2; mt++)
#pragma unroll
                for (int nt = 0; nt < 4; nt++) {
                    MMA(acc[mt][nt], ah[mt], bh[nt]);
                    MMA(acc[mt][nt], al[mt], bh[nt]);
                    MMA(acc[mt][nt], ah[mt], bl[nt]);
                }
        }
    };

    char* st0 = smem;
    char* st1 = smem + STAGE;
    uint32_t su0 = sb, su1 = sb + STAGE;

    // prologue: fill stage 0
    issueA(0);
    issueB(0, su0);
    storeA(st0);
    asm volatile("cp.async.wait_group 0;" ::: "memory");
    __syncthreads();

#pragma unroll 1
    for (int chunk = 0; chunk < NCHUNK; chunk++) {
        int cur = chunk & 1;
        uint32_t scur   = cur ? su1 : su0;
        char*    snext  = cur ? st0 : st1;
        uint32_t sunext = cur ? su0 : su1;
        if (chunk + 1 < NCHUNK) {
            issueA(chunk + 1);               // LDGs in flight during compute
            issueB(chunk + 1, sunext);       // cp.async into other stage
        }
        compute(scur);
        if (chunk + 1 < NCHUNK) {
            storeA(snext);
            asm volatile("cp.async.wait_group 0;" ::: "memory");
        }
        __syncthreads();
    }

    // epilogue
#pragma unroll
    for (int mt = 0; mt < 2; mt++) {
        int r0 = p0 + wm * 32 + mt * 16 + (lid >> 2);
#pragma unroll
        for (int nt = 0; nt < 4; nt++) {
            int col = nblk * 128 + wn * 32 + nt * 8 + (lid & 3) * 2;
            float2* d0 = (float2*)(out + (size_t)r0 * DIM + col);
            float2* d1 = (float2*)(out + (size_t)(r0 + 8) * DIM + col);
            *d0 = make_float2(acc[mt][nt][0], acc[mt][nt][1]);
            *d1 = make_float2(acc[mt][nt][2], acc[mt][nt][3]);
        }
    }
}

// ---------------------------------------------------------------- launch
extern "C" void kernel_launch(void* const* d_in, const int* in_sizes, int n_in,
                              void* d_out, int out_size)
{
    const float* x   = (const float*)d_in[0];
    const float* seg = (const float*)d_in[1];
    const float* wgt = (const float*)d_in[2];
    float* out = (float*)d_out;

    cudaFuncSetAttribute(pconv_mma, cudaFuncAttributeMaxDynamicSharedMemorySize, 2 * STAGE);

    selnorm_kernel<<<P / 256, 256>>>(seg);
    prep_b<<<288, 256>>>(wgt);

    dim3 grid(P / 128, 2);
    pconv_mma<<<grid, 512, 2 * STAGE>>>(x, out);
}

// round 4
// speedup vs baseline: 4.5723x; 1.2962x over previous
#include <cuda_runtime.h>
#include <cuda_bf16.h>
#include <cstdint>

// ---------------------------------------------------------------- constants
#define HH 80
#define WW 80
#define CH 256
#define NC 22
#define DIM 256
#define P 25600              // 4*80*80 pixels
#define NCHUNK 36            // 9 taps * 4 chunks of 64 channels
#define STAGE 65536          // bytes per pipeline stage: Ah 16K | Al 16K | Bh 16K | Bl 16K
#define NSTAGE 3

// device scratch
__device__ float g_seln[P * 9];
__device__ uint4 g_bh[72 * 1024];      // weight smem-images (pre-swizzled)
__device__ uint4 g_bl[72 * 1024];
__device__ uint4 g_xh[4 * P * 8];      // x bf16-hi, [ct][p][g] 16B groups (plain layout)
__device__ uint4 g_xl[4 * P * 8];      // x bf16-lo

// ---------------------------------------------------------------- helpers
static __device__ __forceinline__ uint32_t smem_u32(const void* p) {
    uint32_t a;
    asm("{ .reg .u64 t; cvta.to.shared.u64 t, %1; cvt.u32.u64 %0, t; }" : "=r"(a) : "l"(p));
    return a;
}

#define LDSM4(r, addr) \
    asm volatile("ldmatrix.sync.aligned.m8n8.x4.shared.b16 {%0,%1,%2,%3},[%4];" \
        : "=r"((r)[0]), "=r"((r)[1]), "=r"((r)[2]), "=r"((r)[3]) : "r"(addr))
#define MMA(acc, a, b) \
    asm volatile("mma.sync.aligned.m16n8k16.row.col.f32.bf16.bf16.f32 " \
        "{%0,%1,%2,%3},{%4,%5,%6,%7},{%8,%9},{%0,%1,%2,%3};" \
        : "+f"((acc)[0]), "+f"((acc)[1]), "+f"((acc)[2]), "+f"((acc)[3]) \
        : "r"((a)[0]), "r"((a)[1]), "r"((a)[2]), "r"((a)[3]), "r"((b)[0]), "r"((b)[1]))
#define CPA(dst, src) \
    asm volatile("cp.async.cg.shared.global [%0], [%1], 16;" :: "r"(dst), "l"(src))

// split 8 floats into packed bf16 hi/lo pairs
static __device__ __forceinline__ void split8(const float* v, uint32_t* h4, uint32_t* l4) {
#pragma unroll
    for (int j = 0; j < 4; j++) {
        unsigned short h0 = __bfloat16_as_ushort(__float2bfloat16(v[2*j]));
        unsigned short h1 = __bfloat16_as_ushort(__float2bfloat16(v[2*j+1]));
        float f0 = __uint_as_float((uint32_t)h0 << 16);
        float f1 = __uint_as_float((uint32_t)h1 << 16);
        unsigned short l0 = __bfloat16_as_ushort(__float2bfloat16(v[2*j]   - f0));
        unsigned short l1 = __bfloat16_as_ushort(__float2bfloat16(v[2*j+1] - f1));
        h4[j] = (uint32_t)h0 | ((uint32_t)h1 << 16);
        l4[j] = (uint32_t)l0 | ((uint32_t)l1 << 16);
    }
}

// ---------------------------------------------------------------- kernel 1: selection weights
// 4 lanes per pixel; each lane owns <=6 classes; quad shfl reductions.
__global__ void selnorm_kernel(const float* __restrict__ seg)
{
    int gid = blockIdx.x * blockDim.x + threadIdx.x;   // P*4 threads exactly
    int p = gid >> 2, q = gid & 3;
    int w = p % WW, h = (p / WW) % HH;
    int c0 = q * 6;
    int ncl = (q == 3) ? 4 : 6;

    const float* cp_ = seg + (size_t)p * NC + c0;
    float cv[6];
#pragma unroll
    for (int i = 0; i < 6; i++) cv[i] = (i < ncl) ? cp_[i] : -1e30f;

    float m = cv[0];
#pragma unroll
    for (int i = 1; i < 6; i++) m = fmaxf(m, cv[i]);
    m = fmaxf(m, __shfl_xor_sync(0xffffffffu, m, 1));
    m = fmaxf(m, __shfl_xor_sync(0xffffffffu, m, 2));

    float sel[9];
    int cnt = 0;
#pragma unroll
    for (int k = 0; k < 9; k++) {
        int dh = k / 3 - 1, dw = k % 3 - 1;
        int hh = h + dh, ww = w + dw;
        float s = 0.0f;
        if (hh >= 0 && hh < HH && ww >= 0 && ww < WW) {
            const float* nb = seg + (size_t)(p + dh * WW + dw) * NC + c0;
#pragma unroll
            for (int i = 0; i < 6; i++)
                if (i < ncl && cv[i] == m) s += nb[i];
        }
        s += __shfl_xor_sync(0xffffffffu, s, 1);
        s += __shfl_xor_sync(0xffffffffu, s, 2);
        sel[k] = s;
        if (s != 0.0f) cnt++;
    }
    float nrm = (cnt > 0) ? 9.0f / (float)cnt : 0.0f;
    for (int k = q; k < 9; k += 4) g_seln[p * 9 + k] = sel[k] * nrm;
}

// ---------------------------------------------------------------- kernel 2: weight prep (unchanged layout)
__global__ void prep_b(const float* __restrict__ wgt)
{
    int id = blockIdx.x * blockDim.x + threadIdx.x;   // 73728 threads
    int cc8  = id & 7;
    int row  = (id >> 3) & 127;
    int blk  = id >> 10;           // 0..71
    int nblk = blk & 1;
    int chunk = blk >> 1;
    int ktap = chunk >> 2, ct = chunk & 3;
    int d  = nblk * 128 + row;
    int c0 = ct * 64 + cc8 * 8;

    float v[8];
#pragma unroll
    for (int j = 0; j < 8; j++)
        v[j] = wgt[(size_t)(c0 + j) * (9 * DIM) + ktap * DIM + d];

    uint32_t h4[4], l4[4];
    split8(v, h4, l4);

    int idx = blk * 1024 + row * 8 + (cc8 ^ (row & 7));
    g_bh[idx] = make_uint4(h4[0], h4[1], h4[2], h4[3]);
    g_bl[idx] = make_uint4(l4[0], l4[1], l4[2], l4[3]);
}

// ---------------------------------------------------------------- kernel 2b: x split (once; unscaled)
__global__ void prep_x(const float* __restrict__ x)
{
    int gid = blockIdx.x * blockDim.x + threadIdx.x;   // P*32 threads
    int g8 = gid & 31;          // 8-channel group 0..31
    int p  = gid >> 5;
    int c0 = g8 * 8;
    int ct = c0 >> 6, g = (c0 >> 3) & 7;

    float v[8];
    const float* src = x + (size_t)p * CH + c0;
#pragma unroll
    for (int j = 0; j < 8; j++) v[j] = src[j];

    uint32_t h4[4], l4[4];
    split8(v, h4, l4);

    int idx = (ct * P + p) * 8 + g;
    g_xh[idx] = make_uint4(h4[0], h4[1], h4[2], h4[3]);
    g_xl[idx] = make_uint4(l4[0], l4[1], l4[2], l4[3]);
}

// ---------------------------------------------------------------- kernel 3: HMMA implicit GEMM
// CTA 128(M) x 128(N), 512 threads, 16 warps (4M x 4N), warp tile 32x32.
// All smem fills are cp.async; per-tap partial accumulator scaled by sel_k.
__global__ __launch_bounds__(512, 1) void pconv_mma(float* __restrict__ out)
{
    extern __shared__ __align__(1024) char smem[];
    const uint32_t sb = smem_u32(smem);
    const int tid = threadIdx.x, wid = tid >> 5, lid = tid & 31;
    const int p0 = blockIdx.x * 128;
    const int nblk = blockIdx.y;
    const int wm = wid & 3, wn = wid >> 2;

    // ldmatrix lane addressing
    const int arow = wm * 32 + (lid & 15);
    const int achp = lid >> 4;
    const int bi = lid >> 3;                   // 0..3
    const int bnt = bi >> 1, bkh = bi & 1;
    const int brow = wn * 32 + bnt * 8 + (lid & 7);
    const int bsw  = lid & 7;

    float acc[2][4][4], accT[2][4][4];
#pragma unroll
    for (int i = 0; i < 2; i++)
#pragma unroll
        for (int j = 0; j < 4; j++)
#pragma unroll
            for (int r = 0; r < 4; r++) { acc[i][j][r] = 0.0f; accT[i][j][r] = 0.0f; }

    // A-fill positions: tid and tid+512 over 1024 (row 0..127, group 0..7)
    const int fr0 = tid >> 3, fg0 = tid & 7;
    const int fr1 = (tid + 512) >> 3, fg1 = tid & 7;

    auto fill = [&](int chunk, int s) {
        uint32_t st = sb + s * STAGE;
        int ktap = chunk >> 2, ct = chunk & 3;
        int delta = (ktap / 3 - 1) * WW + (ktap % 3 - 1);
        {
            int nb = p0 + fr0 + delta; nb = nb < 0 ? 0 : (nb >= P ? P - 1 : nb);
            int idx = (ct * P + nb) * 8 + (fg0 ^ (nb & 7));
            uint32_t dst = st + fr0 * 128 + fg0 * 16;
            CPA(dst,         g_xh + idx);
            CPA(dst + 16384, g_xl + idx);
        }
        {
            int nb = p0 + fr1 + delta; nb = nb < 0 ? 0 : (nb >= P ? P - 1 : nb);
            int idx = (ct * P + nb) * 8 + (fg1 ^ (nb & 7));
            uint32_t dst = st + fr1 * 128 + fg1 * 16;
            CPA(dst,         g_xh + idx);
            CPA(dst + 16384, g_xl + idx);
        }
        const uint4* shp = g_bh + (size_t)(chunk * 2 + nblk) * 1024;
        const uint4* slp = g_bl + (size_t)(chunk * 2 + nblk) * 1024;
        CPA(st + 32768 + tid * 16,         shp + tid);
        CPA(st + 32768 + (tid + 512) * 16, shp + tid + 512);
        CPA(st + 49152 + tid * 16,         slp + tid);
        CPA(st + 49152 + (tid + 512) * 16, slp + tid + 512);
        asm volatile("cp.async.commit_group;" ::: "memory");
    };

    auto compute = [&](int chunk, int s) {
        uint32_t st = sb + s * STAGE;
        int ktap = chunk >> 2;
        int delta = (ktap / 3 - 1) * WW + (ktap % 3 - 1);
        int asw = (arow + delta + 128) & 7;       // tap-shifted swizzle phase
        uint32_t Ah = st, Al = st + 16384, Bh = st + 32768, Bl = st + 49152;
#pragma unroll
        for (int ks = 0; ks < 4; ks++) {
            uint32_t ah[2][4], al[2][4], bh[4][2], bl[4][2];
#pragma unroll
            for (int mt = 0; mt < 2; mt++) {
                uint32_t off = (uint32_t)(arow + mt * 16) * 128
                             + (((ks * 2 + achp) ^ asw) << 4);
                LDSM4(ah[mt], Ah + off);
                LDSM4(al[mt], Al + off);
            }
#pragma unroll
            for (int ntp = 0; ntp < 2; ntp++) {
                uint32_t off = (uint32_t)(brow + ntp * 16) * 128
                             + (((ks * 2 + bkh) ^ bsw) << 4);
                uint32_t r[4];
                LDSM4(r, Bh + off);
                bh[ntp*2+0][0] = r[0]; bh[ntp*2+0][1] = r[1];
                bh[ntp*2+1][0] = r[2]; bh[ntp*2+1][1] = r[3];
                LDSM4(r, Bl + off);
                bl[ntp*2+0][0] = r[0]; bl[ntp*2+0][1] = r[1];
                bl[ntp*2+1][0] = r[2]; bl[ntp*2+1][1] = r[3];
            }
#pragma unroll
            for (int mt = 0; mt < 2; mt++)
#pragma unroll
                for (int nt = 0; nt < 4; nt++) {
                    MMA(accT[mt][nt], ah[mt], bh[nt]);
                    MMA(accT[mt][nt], al[mt], bh[nt]);
                    MMA(accT[mt][nt], ah[mt], bl[nt]);
                }
        }
    };

    // prologue
    fill(0, 0);
    fill(1, 1);

#pragma unroll 1
    for (int c = 0; c < NCHUNK; c++) {
        int s = c % NSTAGE;
        if (c + 2 < NCHUNK) fill(c + 2, (c + 2) % NSTAGE);
        if (c < NCHUNK - 2)      asm volatile("cp.async.wait_group 2;" ::: "memory");
        else if (c == NCHUNK - 2) asm volatile("cp.async.wait_group 1;" ::: "memory");
        else                      asm volatile("cp.async.wait_group 0;" ::: "memory");
        __syncthreads();
        compute(c, s);
        if ((c & 3) == 3) {
            int k = c >> 2;
#pragma unroll
            for (int mt = 0; mt < 2; mt++) {
                int rbase = p0 + wm * 32 + mt * 16 + (lid >> 2);
                float s0 = g_seln[rbase * 9 + k];
                float s1 = g_seln[(rbase + 8) * 9 + k];
#pragma unroll
                for (int nt = 0; nt < 4; nt++) {
                    acc[mt][nt][0] += s0 * accT[mt][nt][0];
                    acc[mt][nt][1] += s0 * accT[mt][nt][1];
                    acc[mt][nt][2] += s1 * accT[mt][nt][2];
                    acc[mt][nt][3] += s1 * accT[mt][nt][3];
                    accT[mt][nt][0] = 0.0f; accT[mt][nt][1] = 0.0f;
                    accT[mt][nt][2] = 0.0f; accT[mt][nt][3] = 0.0f;
                }
            }
        }
        __syncthreads();
    }

    // epilogue
#pragma unroll
    for (int mt = 0; mt < 2; mt++) {
        int r0 = p0 + wm * 32 + mt * 16 + (lid >> 2);
#pragma unroll
        for (int nt = 0; nt < 4; nt++) {
            int col = nblk * 128 + wn * 32 + nt * 8 + (lid & 3) * 2;
            float2* d0 = (float2*)(out + (size_t)r0 * DIM + col);
            float2* d1 = (float2*)(out + (size_t)(r0 + 8) * DIM + col);
            *d0 = make_float2(acc[mt][nt][0], acc[mt][nt][1]);
            *d1 = make_float2(acc[mt][nt][2], acc[mt][nt][3]);
        }
    }
}

// ---------------------------------------------------------------- launch
extern "C" void kernel_launch(void* const* d_in, const int* in_sizes, int n_in,
                              void* d_out, int out_size)
{
    const float* x   = (const float*)d_in[0];
    const float* seg = (const float*)d_in[1];
    const float* wgt = (const float*)d_in[2];
    float* out = (float*)d_out;

    cudaFuncSetAttribute(pconv_mma, cudaFuncAttributeMaxDynamicSharedMemorySize,
                         NSTAGE * STAGE);

    selnorm_kernel<<<(P * 4) / 256, 256>>>(seg);
    prep_x<<<(P * 32) / 256, 256>>>(x);
    prep_b<<<288, 256>>>(wgt);

    dim3 grid(P / 128, 2);
    pconv_mma<<<grid, 512, NSTAGE * STAGE>>>(out);
}

// round 5
// speedup vs baseline: 4.9232x; 1.0768x over previous
#include <cuda_runtime.h>
#include <cuda_bf16.h>
#include <cstdint>

// ---------------------------------------------------------------- constants
#define HH 80
#define WW 80
#define CH 256
#define NC 22
#define DIM 256
#define P 25600              // 4*80*80 pixels
#define NCHUNK 36            // 9 taps * 4 chunks of 64 channels
// stage layout: Ah 16K | Al 16K | Bh 8K | Bl 8K
#define STAGE 49152
#define NSTAGE 2

// device scratch
__device__ float g_seln[P * 9];
__device__ uint4 g_bh[144 * 512];      // weight smem-images (pre-swizzled, 8KB blocks)
__device__ uint4 g_bl[144 * 512];
__device__ uint4 g_xh[4 * P * 8];      // x bf16-hi, [ct][p][g] 16B groups
__device__ uint4 g_xl[4 * P * 8];      // x bf16-lo

// ---------------------------------------------------------------- helpers
static __device__ __forceinline__ uint32_t smem_u32(const void* p) {
    uint32_t a;
    asm("{ .reg .u64 t; cvta.to.shared.u64 t, %1; cvt.u32.u64 %0, t; }" : "=r"(a) : "l"(p));
    return a;
}

#define LDSM4(r, addr) \
    asm volatile("ldmatrix.sync.aligned.m8n8.x4.shared.b16 {%0,%1,%2,%3},[%4];" \
        : "=r"((r)[0]), "=r"((r)[1]), "=r"((r)[2]), "=r"((r)[3]) : "r"(addr))
#define MMA(acc, a, b) \
    asm volatile("mma.sync.aligned.m16n8k16.row.col.f32.bf16.bf16.f32 " \
        "{%0,%1,%2,%3},{%4,%5,%6,%7},{%8,%9},{%0,%1,%2,%3};" \
        : "+f"((acc)[0]), "+f"((acc)[1]), "+f"((acc)[2]), "+f"((acc)[3]) \
        : "r"((a)[0]), "r"((a)[1]), "r"((a)[2]), "r"((a)[3]), "r"((b)[0]), "r"((b)[1]))
#define CPA(dst, src) \
    asm volatile("cp.async.cg.shared.global [%0], [%1], 16;" :: "r"(dst), "l"(src))

// split 8 floats into packed bf16 hi/lo pairs
static __device__ __forceinline__ void split8(const float* v, uint32_t* h4, uint32_t* l4) {
#pragma unroll
    for (int j = 0; j < 4; j++) {
        unsigned short h0 = __bfloat16_as_ushort(__float2bfloat16(v[2*j]));
        unsigned short h1 = __bfloat16_as_ushort(__float2bfloat16(v[2*j+1]));
        float f0 = __uint_as_float((uint32_t)h0 << 16);
        float f1 = __uint_as_float((uint32_t)h1 << 16);
        unsigned short l0 = __bfloat16_as_ushort(__float2bfloat16(v[2*j]   - f0));
        unsigned short l1 = __bfloat16_as_ushort(__float2bfloat16(v[2*j+1] - f1));
        h4[j] = (uint32_t)h0 | ((uint32_t)h1 << 16);
        l4[j] = (uint32_t)l0 | ((uint32_t)l1 << 16);
    }
}

// ---------------------------------------------------------------- kernel 1: selection weights
__global__ void selnorm_kernel(const float* __restrict__ seg)
{
    int gid = blockIdx.x * blockDim.x + threadIdx.x;   // P*4 threads
    int p = gid >> 2, q = gid & 3;
    int w = p % WW, h = (p / WW) % HH;
    int c0 = q * 6;
    int ncl = (q == 3) ? 4 : 6;

    const float* cp_ = seg + (size_t)p * NC + c0;
    float cv[6];
#pragma unroll
    for (int i = 0; i < 6; i++) cv[i] = (i < ncl) ? cp_[i] : -1e30f;

    float m = cv[0];
#pragma unroll
    for (int i = 1; i < 6; i++) m = fmaxf(m, cv[i]);
    m = fmaxf(m, __shfl_xor_sync(0xffffffffu, m, 1));
    m = fmaxf(m, __shfl_xor_sync(0xffffffffu, m, 2));

    float sel[9];
    int cnt = 0;
#pragma unroll
    for (int k = 0; k < 9; k++) {
        int dh = k / 3 - 1, dw = k % 3 - 1;
        int hh = h + dh, ww = w + dw;
        float s = 0.0f;
        if (hh >= 0 && hh < HH && ww >= 0 && ww < WW) {
            const float* nb = seg + (size_t)(p + dh * WW + dw) * NC + c0;
#pragma unroll
            for (int i = 0; i < 6; i++)
                if (i < ncl && cv[i] == m) s += nb[i];
        }
        s += __shfl_xor_sync(0xffffffffu, s, 1);
        s += __shfl_xor_sync(0xffffffffu, s, 2);
        sel[k] = s;
        if (s != 0.0f) cnt++;
    }
    float nrm = (cnt > 0) ? 9.0f / (float)cnt : 0.0f;
    for (int k = q; k < 9; k += 4) g_seln[p * 9 + k] = sel[k] * nrm;
}

// ---------------------------------------------------------------- kernel 2: weight prep
// conv_w[c][tap][d] -> per (chunk, nb4) 8KB block: rows = d_local (64),
// cols = channels (64), bf16 hi/lo, SW128 swizzle baked in.
__global__ void prep_b(const float* __restrict__ wgt)
{
    int id = blockIdx.x * blockDim.x + threadIdx.x;   // 73728 threads
    int cc8  = id & 7;
    int row  = (id >> 3) & 63;
    int blk  = id >> 9;            // 0..143
    int nb4  = blk & 3;
    int chunk = blk >> 2;
    int ktap = chunk >> 2, ct = chunk & 3;
    int d  = nb4 * 64 + row;
    int c0 = ct * 64 + cc8 * 8;

    float v[8];
#pragma unroll
    for (int j = 0; j < 8; j++)
        v[j] = wgt[(size_t)(c0 + j) * (9 * DIM) + ktap * DIM + d];

    uint32_t h4[4], l4[4];
    split8(v, h4, l4);

    int idx = blk * 512 + row * 8 + (cc8 ^ (row & 7));
    g_bh[idx] = make_uint4(h4[0], h4[1], h4[2], h4[3]);
    g_bl[idx] = make_uint4(l4[0], l4[1], l4[2], l4[3]);
}

// ---------------------------------------------------------------- kernel 2b: x split (once; unscaled)
__global__ void prep_x(const float* __restrict__ x)
{
    int gid = blockIdx.x * blockDim.x + threadIdx.x;   // P*32 threads
    int g8 = gid & 31;
    int p  = gid >> 5;
    int c0 = g8 * 8;
    int ct = c0 >> 6, g = (c0 >> 3) & 7;

    float v[8];
    const float* src = x + (size_t)p * CH + c0;
#pragma unroll
    for (int j = 0; j < 8; j++) v[j] = src[j];

    uint32_t h4[4], l4[4];
    split8(v, h4, l4);

    int idx = (ct * P + p) * 8 + g;
    g_xh[idx] = make_uint4(h4[0], h4[1], h4[2], h4[3]);
    g_xl[idx] = make_uint4(l4[0], l4[1], l4[2], l4[3]);
}

// ---------------------------------------------------------------- kernel 3: HMMA implicit GEMM
// CTA 128(M) x 64(N), 256 threads, 8 warps (4M x 2N), warp tile 32x32.
// 2 CTAs co-resident per SM; one barrier per chunk; 2-stage cp.async pipeline.
__global__ __launch_bounds__(256, 2) void pconv_mma(float* __restrict__ out)
{
    extern __shared__ __align__(1024) char smem[];
    const uint32_t sb = smem_u32(smem);
    const int tid = threadIdx.x, wid = tid >> 5, lid = tid & 31;
    const int p0 = blockIdx.x * 128;
    const int nblk = blockIdx.y;            // 0..3 (64-wide N block)
    const int wm = wid & 3, wn = wid >> 2;  // 4 M-quarters x 2 N-halves

    // ldmatrix lane addressing
    const int arow = wm * 32 + (lid & 15);
    const int achp = lid >> 4;
    const int bi = lid >> 3;                   // 0..3
    const int bnt = bi >> 1, bkh = bi & 1;
    const int brow = wn * 32 + bnt * 8 + (lid & 7);
    const int bsw  = lid & 7;

    float acc[2][4][4], accT[2][4][4];
#pragma unroll
    for (int i = 0; i < 2; i++)
#pragma unroll
        for (int j = 0; j < 4; j++)
#pragma unroll
            for (int r = 0; r < 4; r++) { acc[i][j][r] = 0.0f; accT[i][j][r] = 0.0f; }

    auto fill = [&](int chunk, int s) {
        uint32_t st = sb + s * STAGE;
        int ktap = chunk >> 2, ct = chunk & 3;
        int delta = (ktap / 3 - 1) * WW + (ktap % 3 - 1);
        // A: 1024 uint4 per plane, 256 threads -> 4 iters
#pragma unroll
        for (int i = 0; i < 4; i++) {
            int u = tid + i * 256;
            int fr = u >> 3, fg = u & 7;
            int nb = p0 + fr + delta; nb = nb < 0 ? 0 : (nb >= P ? P - 1 : nb);
            int idx = (ct * P + nb) * 8 + (fg ^ (nb & 7));
            uint32_t dst = st + fr * 128 + fg * 16;
            CPA(dst,         g_xh + idx);
            CPA(dst + 16384, g_xl + idx);
        }
        // B: 512 uint4 per plane -> 2 iters
        const uint4* shp = g_bh + (size_t)(chunk * 4 + nblk) * 512;
        const uint4* slp = g_bl + (size_t)(chunk * 4 + nblk) * 512;
        CPA(st + 32768 + tid * 16,         shp + tid);
        CPA(st + 32768 + (tid + 256) * 16, shp + tid + 256);
        CPA(st + 40960 + tid * 16,         slp + tid);
        CPA(st + 40960 + (tid + 256) * 16, slp + tid + 256);
        asm volatile("cp.async.commit_group;" ::: "memory");
    };

    auto compute = [&](int chunk, int s) {
        uint32_t st = sb + s * STAGE;
        int ktap = chunk >> 2;
        int delta = (ktap / 3 - 1) * WW + (ktap % 3 - 1);
        int asw = (arow + delta + 128) & 7;       // tap-shifted swizzle phase
        uint32_t Ah = st, Al = st + 16384, Bh = st + 32768, Bl = st + 40960;
#pragma unroll
        for (int ks = 0; ks < 4; ks++) {
            uint32_t ah[2][4], al[2][4], bh[4][2], bl[4][2];
#pragma unroll
            for (int mt = 0; mt < 2; mt++) {
                uint32_t off = (uint32_t)(arow + mt * 16) * 128
                             + (((ks * 2 + achp) ^ asw) << 4);
                LDSM4(ah[mt], Ah + off);
                LDSM4(al[mt], Al + off);
            }
#pragma unroll
            for (int ntp = 0; ntp < 2; ntp++) {
                uint32_t off = (uint32_t)(brow + ntp * 16) * 128
                             + (((ks * 2 + bkh) ^ bsw) << 4);
                uint32_t r[4];
                LDSM4(r, Bh + off);
                bh[ntp*2+0][0] = r[0]; bh[ntp*2+0][1] = r[1];
                bh[ntp*2+1][0] = r[2]; bh[ntp*2+1][1] = r[3];
                LDSM4(r, Bl + off);
                bl[ntp*2+0][0] = r[0]; bl[ntp*2+0][1] = r[1];
                bl[ntp*2+1][0] = r[2]; bl[ntp*2+1][1] = r[3];
            }
#pragma unroll
            for (int mt = 0; mt < 2; mt++)
#pragma unroll
                for (int nt = 0; nt < 4; nt++) {
                    MMA(accT[mt][nt], ah[mt], bh[nt]);
                    MMA(accT[mt][nt], al[mt], bh[nt]);
                    MMA(accT[mt][nt], ah[mt], bl[nt]);
                }
        }
    };

    // prologue: stage 0
    fill(0, 0);

#pragma unroll 1
    for (int c = 0; c < NCHUNK; c++) {
        int s = c & 1;
        asm volatile("cp.async.wait_group 0;" ::: "memory");   // fill(c) complete
        __syncthreads();                                       // publishes fill(c); retires stage s^1
        if (c + 1 < NCHUNK) fill(c + 1, s ^ 1);
        compute(c, s);
        if ((c & 3) == 3) {
            int k = c >> 2;
#pragma unroll
            for (int mt = 0; mt < 2; mt++) {
                int rbase = p0 + wm * 32 + mt * 16 + (lid >> 2);
                float s0 = g_seln[rbase * 9 + k];
                float s1 = g_seln[(rbase + 8) * 9 + k];
#pragma unroll
                for (int nt = 0; nt < 4; nt++) {
                    acc[mt][nt][0] += s0 * accT[mt][nt][0];
                    acc[mt][nt][1] += s0 * accT[mt][nt][1];
                    acc[mt][nt][2] += s1 * accT[mt][nt][2];
                    acc[mt][nt][3] += s1 * accT[mt][nt][3];
                    accT[mt][nt][0] = 0.0f; accT[mt][nt][1] = 0.0f;
                    accT[mt][nt][2] = 0.0f; accT[mt][nt][3] = 0.0f;
                }
            }
        }
    }

    // epilogue
#pragma unroll
    for (int mt = 0; mt < 2; mt++) {
        int r0 = p0 + wm * 32 + mt * 16 + (lid >> 2);
#pragma unroll
        for (int nt = 0; nt < 4; nt++) {
            int col = nblk * 64 + wn * 32 + nt * 8 + (lid & 3) * 2;
            float2* d0 = (float2*)(out + (size_t)r0 * DIM + col);
            float2* d1 = (float2*)(out + (size_t)(r0 + 8) * DIM + col);
            *d0 = make_float2(acc[mt][nt][0], acc[mt][nt][1]);
            *d1 = make_float2(acc[mt][nt][2], acc[mt][nt][3]);
        }
    }
}

// ---------------------------------------------------------------- launch
extern "C" void kernel_launch(void* const* d_in, const int* in_sizes, int n_in,
                              void* d_out, int out_size)
{
    const float* x   = (const float*)d_in[0];
    const float* seg = (const float*)d_in[1];
    const float* wgt = (const float*)d_in[2];
    float* out = (float*)d_out;

    cudaFuncSetAttribute(pconv_mma, cudaFuncAttributeMaxDynamicSharedMemorySize,
                         NSTAGE * STAGE);

    selnorm_kernel<<<(P * 4) / 256, 256>>>(seg);
    prep_x<<<(P * 32) / 256, 256>>>(x);
    prep_b<<<288, 256>>>(wgt);

    dim3 grid(P / 128, 4);
    pconv_mma<<<grid, 256, NSTAGE * STAGE>>>(out);
}

// round 6
// speedup vs baseline: 6.8410x; 1.3895x over previous
#include <cuda_runtime.h>
#include <cuda_fp16.h>
#include <cstdint>

// ---------------------------------------------------------------- constants
#define HH 80
#define WW 80
#define CH 256
#define NC 22
#define DIM 256
#define P 25600              // 4*80*80 pixels
#define NCHUNK 36            // 9 taps * 4 chunks of 64 channels
// stage layout: A 16K | Bh 8K | Bl 8K
#define STAGE 32768
#define NSTAGE 3

// device scratch
__device__ float g_seln[P * 9];
__device__ uint4 g_bh[144 * 512];      // weight fp16-hi smem-images (pre-swizzled 8KB blocks)
__device__ uint4 g_bl[144 * 512];      // weight fp16-lo residual
__device__ uint4 g_xh[4 * P * 8];      // x fp16, [ct][p][g] 16B groups

// ---------------------------------------------------------------- helpers
static __device__ __forceinline__ uint32_t smem_u32(const void* p) {
    uint32_t a;
    asm("{ .reg .u64 t; cvta.to.shared.u64 t, %1; cvt.u32.u64 %0, t; }" : "=r"(a) : "l"(p));
    return a;
}

#define LDSM4(r, addr) \
    asm volatile("ldmatrix.sync.aligned.m8n8.x4.shared.b16 {%0,%1,%2,%3},[%4];" \
        : "=r"((r)[0]), "=r"((r)[1]), "=r"((r)[2]), "=r"((r)[3]) : "r"(addr))
#define MMA(acc, a, b) \
    asm volatile("mma.sync.aligned.m16n8k16.row.col.f32.f16.f16.f32 " \
        "{%0,%1,%2,%3},{%4,%5,%6,%7},{%8,%9},{%0,%1,%2,%3};" \
        : "+f"((acc)[0]), "+f"((acc)[1]), "+f"((acc)[2]), "+f"((acc)[3]) \
        : "r"((a)[0]), "r"((a)[1]), "r"((a)[2]), "r"((a)[3]), "r"((b)[0]), "r"((b)[1]))
#define CPA(dst, src) \
    asm volatile("cp.async.cg.shared.global [%0], [%1], 16;" :: "r"(dst), "l"(src))

// fp16 hi/lo split of 8 floats -> packed pairs
static __device__ __forceinline__ void split8h(const float* v, uint32_t* h4, uint32_t* l4) {
#pragma unroll
    for (int j = 0; j < 4; j++) {
        __half h0 = __float2half_rn(v[2*j]);
        __half h1 = __float2half_rn(v[2*j+1]);
        __half l0 = __float2half_rn(v[2*j]   - __half2float(h0));
        __half l1 = __float2half_rn(v[2*j+1] - __half2float(h1));
        h4[j] = (uint32_t)__half_as_ushort(h0) | ((uint32_t)__half_as_ushort(h1) << 16);
        l4[j] = (uint32_t)__half_as_ushort(l0) | ((uint32_t)__half_as_ushort(l1) << 16);
    }
}

// ---------------------------------------------------------------- kernel 1: selection weights
__global__ void selnorm_kernel(const float* __restrict__ seg)
{
    int gid = blockIdx.x * blockDim.x + threadIdx.x;   // P*4 threads
    int p = gid >> 2, q = gid & 3;
    int w = p % WW, h = (p / WW) % HH;
    int c0 = q * 6;
    int ncl = (q == 3) ? 4 : 6;

    const float* cp_ = seg + (size_t)p * NC + c0;
    float cv[6];
#pragma unroll
    for (int i = 0; i < 6; i++) cv[i] = (i < ncl) ? cp_[i] : -1e30f;

    float m = cv[0];
#pragma unroll
    for (int i = 1; i < 6; i++) m = fmaxf(m, cv[i]);
    m = fmaxf(m, __shfl_xor_sync(0xffffffffu, m, 1));
    m = fmaxf(m, __shfl_xor_sync(0xffffffffu, m, 2));

    float sel[9];
    int cnt = 0;
#pragma unroll
    for (int k = 0; k < 9; k++) {
        int dh = k / 3 - 1, dw = k % 3 - 1;
        int hh = h + dh, ww = w + dw;
        float s = 0.0f;
        if (hh >= 0 && hh < HH && ww >= 0 && ww < WW) {
            const float* nb = seg + (size_t)(p + dh * WW + dw) * NC + c0;
#pragma unroll
            for (int i = 0; i < 6; i++)
                if (i < ncl && cv[i] == m) s += nb[i];
        }
        s += __shfl_xor_sync(0xffffffffu, s, 1);
        s += __shfl_xor_sync(0xffffffffu, s, 2);
        sel[k] = s;
        if (s != 0.0f) cnt++;
    }
    float nrm = (cnt > 0) ? 9.0f / (float)cnt : 0.0f;
    for (int k = q; k < 9; k += 4) g_seln[p * 9 + k] = sel[k] * nrm;
}

// ---------------------------------------------------------------- kernel 2: weight prep (fp16 hi/lo)
// conv_w[c][tap][d] -> per (chunk, nb4) 8KB block: rows = d_local (64),
// cols = channels (64), SW128 swizzle baked in.
__global__ void prep_b(const float* __restrict__ wgt)
{
    int id = blockIdx.x * blockDim.x + threadIdx.x;   // 73728 threads
    int cc8  = id & 7;
    int row  = (id >> 3) & 63;
    int blk  = id >> 9;            // 0..143
    int nb4  = blk & 3;
    int chunk = blk >> 2;
    int ktap = chunk >> 2, ct = chunk & 3;
    int d  = nb4 * 64 + row;
    int c0 = ct * 64 + cc8 * 8;

    float v[8];
#pragma unroll
    for (int j = 0; j < 8; j++)
        v[j] = wgt[(size_t)(c0 + j) * (9 * DIM) + ktap * DIM + d];

    uint32_t h4[4], l4[4];
    split8h(v, h4, l4);

    int idx = blk * 512 + row * 8 + (cc8 ^ (row & 7));
    g_bh[idx] = make_uint4(h4[0], h4[1], h4[2], h4[3]);
    g_bl[idx] = make_uint4(l4[0], l4[1], l4[2], l4[3]);
}

// ---------------------------------------------------------------- kernel 2b: x -> fp16 (once)
__global__ void prep_x(const float* __restrict__ x)
{
    int gid = blockIdx.x * blockDim.x + threadIdx.x;   // P*32 threads
    int g8 = gid & 31;
    int p  = gid >> 5;
    int c0 = g8 * 8;
    int ct = c0 >> 6, g = (c0 >> 3) & 7;

    const float* src = x + (size_t)p * CH + c0;
    uint32_t h4[4];
#pragma unroll
    for (int j = 0; j < 4; j++) {
        __half h0 = __float2half_rn(src[2*j]);
        __half h1 = __float2half_rn(src[2*j+1]);
        h4[j] = (uint32_t)__half_as_ushort(h0) | ((uint32_t)__half_as_ushort(h1) << 16);
    }
    g_xh[(ct * P + p) * 8 + g] = make_uint4(h4[0], h4[1], h4[2], h4[3]);
}

// ---------------------------------------------------------------- kernel 3: HMMA implicit GEMM
// CTA 128(M) x 64(N), 256 threads, 8 warps (4M x 2N), warp tile 32x32.
// fp16 2-product: out = a * (bh + bl) with a = fp16(x) single plane.
// 2 CTAs/SM, 3-stage cp.async pipeline, one barrier per chunk.
__global__ __launch_bounds__(256, 2) void pconv_mma(float* __restrict__ out)
{
    extern __shared__ __align__(1024) char smem[];
    const uint32_t sb = smem_u32(smem);
    const int tid = threadIdx.x, wid = tid >> 5, lid = tid & 31;
    const int p0 = blockIdx.x * 128;
    const int nblk = blockIdx.y;            // 0..3 (64-wide N block)
    const int wm = wid & 3, wn = wid >> 2;  // 4 M-quarters x 2 N-halves

    // ldmatrix lane addressing
    const int arow = wm * 32 + (lid & 15);
    const int achp = lid >> 4;
    const int bi = lid >> 3;                   // 0..3
    const int bnt = bi >> 1, bkh = bi & 1;
    const int brow = wn * 32 + bnt * 8 + (lid & 7);
    const int bsw  = lid & 7;

    float acc[2][4][4], accT[2][4][4];
#pragma unroll
    for (int i = 0; i < 2; i++)
#pragma unroll
        for (int j = 0; j < 4; j++)
#pragma unroll
            for (int r = 0; r < 4; r++) { acc[i][j][r] = 0.0f; accT[i][j][r] = 0.0f; }

    auto fill = [&](int chunk, int s) {
        uint32_t st = sb + s * STAGE;
        int ktap = chunk >> 2, ct = chunk & 3;
        int delta = (ktap / 3 - 1) * WW + (ktap % 3 - 1);
        // A: 1024 uint4, 256 threads -> 4 iters
#pragma unroll
        for (int i = 0; i < 4; i++) {
            int u = tid + i * 256;
            int fr = u >> 3, fg = u & 7;
            int nb = p0 + fr + delta; nb = nb < 0 ? 0 : (nb >= P ? P - 1 : nb);
            int idx = (ct * P + nb) * 8 + (fg ^ (nb & 7));
            CPA(st + fr * 128 + fg * 16, g_xh + idx);
        }
        // B: 512 uint4 per plane -> 2 iters each
        const uint4* shp = g_bh + (size_t)(chunk * 4 + nblk) * 512;
        const uint4* slp = g_bl + (size_t)(chunk * 4 + nblk) * 512;
        CPA(st + 16384 + tid * 16,         shp + tid);
        CPA(st + 16384 + (tid + 256) * 16, shp + tid + 256);
        CPA(st + 24576 + tid * 16,         slp + tid);
        CPA(st + 24576 + (tid + 256) * 16, slp + tid + 256);
        asm volatile("cp.async.commit_group;" ::: "memory");
    };

    auto compute = [&](int chunk, int s) {
        uint32_t st = sb + s * STAGE;
        int ktap = chunk >> 2;
        int delta = (ktap / 3 - 1) * WW + (ktap % 3 - 1);
        int asw = (arow + delta + 128) & 7;       // tap-shifted swizzle phase
        uint32_t Ap = st, Bh = st + 16384, Bl = st + 24576;
#pragma unroll
        for (int ks = 0; ks < 4; ks++) {
            uint32_t a[2][4], bh[4][2], bl[4][2];
#pragma unroll
            for (int mt = 0; mt < 2; mt++) {
                uint32_t off = (uint32_t)(arow + mt * 16) * 128
                             + (((ks * 2 + achp) ^ asw) << 4);
                LDSM4(a[mt], Ap + off);
            }
#pragma unroll
            for (int ntp = 0; ntp < 2; ntp++) {
                uint32_t off = (uint32_t)(brow + ntp * 16) * 128
                             + (((ks * 2 + bkh) ^ bsw) << 4);
                uint32_t r[4];
                LDSM4(r, Bh + off);
                bh[ntp*2+0][0] = r[0]; bh[ntp*2+0][1] = r[1];
                bh[ntp*2+1][0] = r[2]; bh[ntp*2+1][1] = r[3];
                LDSM4(r, Bl + off);
                bl[ntp*2+0][0] = r[0]; bl[ntp*2+0][1] = r[1];
                bl[ntp*2+1][0] = r[2]; bl[ntp*2+1][1] = r[3];
            }
#pragma unroll
            for (int mt = 0; mt < 2; mt++)
#pragma unroll
                for (int nt = 0; nt < 4; nt++) {
                    MMA(accT[mt][nt], a[mt], bh[nt]);
                    MMA(accT[mt][nt], a[mt], bl[nt]);
                }
        }
    };

    // prologue: stages 0,1
    fill(0, 0);
    fill(1, 1);

#pragma unroll 1
    for (int c = 0; c < NCHUNK; c++) {
        int s = c % NSTAGE;
        if (c < NCHUNK - 1) asm volatile("cp.async.wait_group 1;" ::: "memory");
        else                asm volatile("cp.async.wait_group 0;" ::: "memory");
        __syncthreads();    // publishes fill(c); all compute(c-1) readers done
        if (c + 2 < NCHUNK) fill(c + 2, (c + 2) % NSTAGE);
        compute(c, s);
        if ((c & 3) == 3) {
            int k = c >> 2;
#pragma unroll
            for (int mt = 0; mt < 2; mt++) {
                int rbase = p0 + wm * 32 + mt * 16 + (lid >> 2);
                float s0 = g_seln[rbase * 9 + k];
                float s1 = g_seln[(rbase + 8) * 9 + k];
#pragma unroll
                for (int nt = 0; nt < 4; nt++) {
                    acc[mt][nt][0] += s0 * accT[mt][nt][0];
                    acc[mt][nt][1] += s0 * accT[mt][nt][1];
                    acc[mt][nt][2] += s1 * accT[mt][nt][2];
                    acc[mt][nt][3] += s1 * accT[mt][nt][3];
                    accT[mt][nt][0] = 0.0f; accT[mt][nt][1] = 0.0f;
                    accT[mt][nt][2] = 0.0f; accT[mt][nt][3] = 0.0f;
                }
            }
        }
    }

    // epilogue
#pragma unroll
    for (int mt = 0; mt < 2; mt++) {
        int r0 = p0 + wm * 32 + mt * 16 + (lid >> 2);
#pragma unroll
        for (int nt = 0; nt < 4; nt++) {
            int col = nblk * 64 + wn * 32 + nt * 8 + (lid & 3) * 2;
            float2* d0 = (float2*)(out + (size_t)r0 * DIM + col);
            float2* d1 = (float2*)(out + (size_t)(r0 + 8) * DIM + col);
            *d0 = make_float2(acc[mt][nt][0], acc[mt][nt][1]);
            *d1 = make_float2(acc[mt][nt][2], acc[mt][nt][3]);
        }
    }
}

// ---------------------------------------------------------------- launch
extern "C" void kernel_launch(void* const* d_in, const int* in_sizes, int n_in,
                              void* d_out, int out_size)
{
    const float* x   = (const float*)d_in[0];
    const float* seg = (const float*)d_in[1];
    const float* wgt = (const float*)d_in[2];
    float* out = (float*)d_out;

    cudaFuncSetAttribute(pconv_mma, cudaFuncAttributeMaxDynamicSharedMemorySize,
                         NSTAGE * STAGE);

    selnorm_kernel<<<(P * 4) / 256, 256>>>(seg);
    prep_x<<<(P * 32) / 256, 256>>>(x);
    prep_b<<<288, 256>>>(wgt);

    dim3 grid(P / 128, 4);
    pconv_mma<<<grid, 256, NSTAGE * STAGE>>>(out);
}

// round 7
// speedup vs baseline: 11.5178x; 1.6836x over previous
#include <cuda_runtime.h>
#include <cuda_fp16.h>
#include <cstdint>

// ---------------------------------------------------------------- constants
#define HH 80
#define WW 80
#define CH 256
#define NC 22
#define DIM 256
#define P 25600              // 4*80*80 pixels
#define NCHUNK 36            // 9 taps * 4 chunks of 64 channels
// stage layout: A 16K | B 16K
#define STAGE 32768
#define NSTAGE 3

// device scratch
__device__ float g_seln[P * 9];
__device__ uint4 g_w[144 * 512];       // weight fp16 smem-images (pre-swizzled 8KB blocks)
__device__ uint4 g_xf[4 * P * 8];      // x fp16, [ct][p][g] 16B groups

// ---------------------------------------------------------------- helpers
static __device__ __forceinline__ uint32_t smem_u32(const void* p) {
    uint32_t a;
    asm("{ .reg .u64 t; cvta.to.shared.u64 t, %1; cvt.u32.u64 %0, t; }" : "=r"(a) : "l"(p));
    return a;
}

#define LDSM4(r, addr) \
    asm volatile("ldmatrix.sync.aligned.m8n8.x4.shared.b16 {%0,%1,%2,%3},[%4];" \
        : "=r"((r)[0]), "=r"((r)[1]), "=r"((r)[2]), "=r"((r)[3]) : "r"(addr))
#define MMA(acc, a, b) \
    asm volatile("mma.sync.aligned.m16n8k16.row.col.f32.f16.f16.f32 " \
        "{%0,%1,%2,%3},{%4,%5,%6,%7},{%8,%9},{%0,%1,%2,%3};" \
        : "+f"((acc)[0]), "+f"((acc)[1]), "+f"((acc)[2]), "+f"((acc)[3]) \
        : "r"((a)[0]), "r"((a)[1]), "r"((a)[2]), "r"((a)[3]), "r"((b)[0]), "r"((b)[1]))
#define CPA(dst, src) \
    asm volatile("cp.async.cg.shared.global [%0], [%1], 16;" :: "r"(dst), "l"(src))

static __device__ __forceinline__ uint32_t hmul2u(uint32_t a, uint32_t s) {
    uint32_t r;
    asm("mul.rn.f16x2 %0, %1, %2;" : "=r"(r) : "r"(a), "r"(s));
    return r;
}

// ---------------------------------------------------------------- fused prep kernel
// blocks [0,400): selnorm (4 lanes/pixel)
// blocks [400,3600): x -> fp16
// blocks [3600,3888): weight -> fp16 smem-image
__global__ void prep_all(const float* __restrict__ x,
                         const float* __restrict__ seg,
                         const float* __restrict__ wgt)
{
    int b = blockIdx.x;
    if (b < 400) {
        // ---- selnorm ----
        int gid = b * 256 + threadIdx.x;       // P*4 threads
        int p = gid >> 2, q = gid & 3;
        int w = p % WW, h = (p / WW) % HH;
        int c0 = q * 6;
        int ncl = (q == 3) ? 4 : 6;

        const float* cp_ = seg + (size_t)p * NC + c0;
        float cv[6];
#pragma unroll
        for (int i = 0; i < 6; i++) cv[i] = (i < ncl) ? cp_[i] : -1e30f;

        float m = cv[0];
#pragma unroll
        for (int i = 1; i < 6; i++) m = fmaxf(m, cv[i]);
        m = fmaxf(m, __shfl_xor_sync(0xffffffffu, m, 1));
        m = fmaxf(m, __shfl_xor_sync(0xffffffffu, m, 2));

        float sel[9];
        int cnt = 0;
#pragma unroll
        for (int k = 0; k < 9; k++) {
            int dh = k / 3 - 1, dw = k % 3 - 1;
            int hh = h + dh, ww = w + dw;
            float s = 0.0f;
            if (hh >= 0 && hh < HH && ww >= 0 && ww < WW) {
                const float* nb = seg + (size_t)(p + dh * WW + dw) * NC + c0;
#pragma unroll
                for (int i = 0; i < 6; i++)
                    if (i < ncl && cv[i] == m) s += nb[i];
            }
            s += __shfl_xor_sync(0xffffffffu, s, 1);
            s += __shfl_xor_sync(0xffffffffu, s, 2);
            sel[k] = s;
            if (s != 0.0f) cnt++;
        }
        float nrm = (cnt > 0) ? 9.0f / (float)cnt : 0.0f;
        for (int k = q; k < 9; k += 4) g_seln[p * 9 + k] = sel[k] * nrm;
    } else if (b < 3600) {
        // ---- x -> fp16 ----
        int gid = (b - 400) * 256 + threadIdx.x;   // P*32 threads
        int g8 = gid & 31;
        int p  = gid >> 5;
        int c0 = g8 * 8;
        int ct = c0 >> 6, g = (c0 >> 3) & 7;

        const float* src = x + (size_t)p * CH + c0;
        uint32_t h4[4];
#pragma unroll
        for (int j = 0; j < 4; j++) {
            __half h0 = __float2half_rn(src[2*j]);
            __half h1 = __float2half_rn(src[2*j+1]);
            h4[j] = (uint32_t)__half_as_ushort(h0) | ((uint32_t)__half_as_ushort(h1) << 16);
        }
        g_xf[(ct * P + p) * 8 + g] = make_uint4(h4[0], h4[1], h4[2], h4[3]);
    } else {
        // ---- weight -> fp16 pre-swizzled image ----
        int id = (b - 3600) * 256 + threadIdx.x;   // 73728 threads
        int cc8  = id & 7;
        int row  = (id >> 3) & 63;
        int blk  = id >> 9;            // 0..143
        int nb4  = blk & 3;
        int chunk = blk >> 2;
        int ktap = chunk >> 2, ct = chunk & 3;
        int d  = nb4 * 64 + row;
        int c0 = ct * 64 + cc8 * 8;

        uint32_t h4[4];
#pragma unroll
        for (int j = 0; j < 4; j++) {
            float v0 = wgt[(size_t)(c0 + 2*j)     * (9 * DIM) + ktap * DIM + d];
            float v1 = wgt[(size_t)(c0 + 2*j + 1) * (9 * DIM) + ktap * DIM + d];
            __half h0 = __float2half_rn(v0);
            __half h1 = __float2half_rn(v1);
            h4[j] = (uint32_t)__half_as_ushort(h0) | ((uint32_t)__half_as_ushort(h1) << 16);
        }
        int idx = blk * 512 + row * 8 + (cc8 ^ (row & 7));
        g_w[idx] = make_uint4(h4[0], h4[1], h4[2], h4[3]);
    }
}

// ---------------------------------------------------------------- HMMA implicit GEMM
// CTA 128(M) x 128(N), 256 threads, 8 warps (4M x 2N), warp tile 32x64.
// Single fp16 plane for both operands; sel folded into A fragments (HMUL2).
// 2 CTAs/SM, 3-stage cp.async pipeline, one barrier per chunk.
__global__ __launch_bounds__(256, 2) void pconv_mma(float* __restrict__ out)
{
    extern __shared__ __align__(1024) char smem[];
    const uint32_t sb = smem_u32(smem);
    const int tid = threadIdx.x, wid = tid >> 5, lid = tid & 31;
    const int p0 = blockIdx.x * 128;
    const int nblk = blockIdx.y;            // 0..1 (128-wide N block)
    const int wm = wid & 3, wn = wid >> 2;  // 4 M-quarters x 2 N-halves(64)

    // ldmatrix lane addressing
    const int arow = wm * 32 + (lid & 15);
    const int achp = lid >> 4;
    const int bi = lid >> 3;                   // 0..3
    const int bnt = bi >> 1, bkh = bi & 1;
    const int brow = wn * 64 + bnt * 8 + (lid & 7);
    const int bsw  = lid & 7;

    // sel rows for this lane (per mt tile: rows r, r+8)
    const int selr0 = p0 + wm * 32 + (lid >> 2);

    float acc[2][8][4];
#pragma unroll
    for (int i = 0; i < 2; i++)
#pragma unroll
        for (int j = 0; j < 8; j++)
#pragma unroll
            for (int r = 0; r < 4; r++) acc[i][j][r] = 0.0f;

    auto fill = [&](int chunk, int s) {
        uint32_t st = sb + s * STAGE;
        int ktap = chunk >> 2, ct = chunk & 3;
        int delta = (ktap / 3 - 1) * WW + (ktap % 3 - 1);
        // A: 1024 uint4, 256 threads -> 4 iters
#pragma unroll
        for (int i = 0; i < 4; i++) {
            int u = tid + i * 256;
            int fr = u >> 3, fg = u & 7;
            int nb = p0 + fr + delta; nb = nb < 0 ? 0 : (nb >= P ? P - 1 : nb);
            int idx = (ct * P + nb) * 8 + (fg ^ (nb & 7));
            CPA(st + fr * 128 + fg * 16, g_xf + idx);
        }
        // B: 1024 uint4 (two 8KB blocks: d rows 0..127 of this nblk)
        const uint4* wp = g_w + (size_t)(chunk * 4 + nblk * 2) * 512;
#pragma unroll
        for (int i = 0; i < 4; i++)
            CPA(st + 16384 + (tid + i * 256) * 16, wp + tid + i * 256);
        asm volatile("cp.async.commit_group;" ::: "memory");
    };

    // per-tap sel as broadcast half2 (4 values: mt{0,1} x {lo,hi} rows)
    uint32_t selh[2][2];

    auto load_sel = [&](int ktap) {
#pragma unroll
        for (int mt = 0; mt < 2; mt++) {
            float s0 = g_seln[(selr0 + mt * 16) * 9 + ktap];
            float s1 = g_seln[(selr0 + mt * 16 + 8) * 9 + ktap];
            __half2 h0 = __float2half2_rn(s0);
            __half2 h1 = __float2half2_rn(s1);
            selh[mt][0] = *reinterpret_cast<uint32_t*>(&h0);
            selh[mt][1] = *reinterpret_cast<uint32_t*>(&h1);
        }
    };

    auto compute = [&](int chunk, int s) {
        uint32_t st = sb + s * STAGE;
        int ktap = chunk >> 2;
        int delta = (ktap / 3 - 1) * WW + (ktap % 3 - 1);
        int asw = (arow + delta + 128) & 7;       // tap-shifted swizzle phase
        uint32_t Ap = st, Bp = st + 16384;
#pragma unroll
        for (int ks = 0; ks < 4; ks++) {
            uint32_t a[2][4], bfr[8][2];
#pragma unroll
            for (int mt = 0; mt < 2; mt++) {
                uint32_t off = (uint32_t)(arow + mt * 16) * 128
                             + (((ks * 2 + achp) ^ asw) << 4);
                LDSM4(a[mt], Ap + off);
                // fold sel into A: a0,a2 = row lo; a1,a3 = row hi
                a[mt][0] = hmul2u(a[mt][0], selh[mt][0]);
                a[mt][2] = hmul2u(a[mt][2], selh[mt][0]);
                a[mt][1] = hmul2u(a[mt][1], selh[mt][1]);
                a[mt][3] = hmul2u(a[mt][3], selh[mt][1]);
            }
#pragma unroll
            for (int ntp = 0; ntp < 4; ntp++) {
                uint32_t off = (uint32_t)(brow + ntp * 16) * 128
                             + (((ks * 2 + bkh) ^ bsw) << 4);
                uint32_t r[4];
                LDSM4(r, Bp + off);
                bfr[ntp*2+0][0] = r[0]; bfr[ntp*2+0][1] = r[1];
                bfr[ntp*2+1][0] = r[2]; bfr[ntp*2+1][1] = r[3];
            }
#pragma unroll
            for (int mt = 0; mt < 2; mt++)
#pragma unroll
                for (int nt = 0; nt < 8; nt++)
                    MMA(acc[mt][nt], a[mt], bfr[nt]);
        }
    };

    // prologue: stages 0,1
    fill(0, 0);
    fill(1, 1);

#pragma unroll 1
    for (int c = 0; c < NCHUNK; c++) {
        int s = c % NSTAGE;
        if ((c & 3) == 0) load_sel(c >> 2);
        if (c < NCHUNK - 1) asm volatile("cp.async.wait_group 1;" ::: "memory");
        else                asm volatile("cp.async.wait_group 0;" ::: "memory");
        __syncthreads();    // publishes fill(c); all compute(c-1) readers done
        if (c + 2 < NCHUNK) fill(c + 2, (c + 2) % NSTAGE);
        compute(c, s);
    }

    // epilogue
#pragma unroll
    for (int mt = 0; mt < 2; mt++) {
        int r0 = p0 + wm * 32 + mt * 16 + (lid >> 2);
#pragma unroll
        for (int nt = 0; nt < 8; nt++) {
            int col = nblk * 128 + wn * 64 + nt * 8 + (lid & 3) * 2;
            float2* d0 = (float2*)(out + (size_t)r0 * DIM + col);
            float2* d1 = (float2*)(out + (size_t)(r0 + 8) * DIM + col);
            *d0 = make_float2(acc[mt][nt][0], acc[mt][nt][1]);
            *d1 = make_float2(acc[mt][nt][2], acc[mt][nt][3]);
        }
    }
}

// ---------------------------------------------------------------- launch
extern "C" void kernel_launch(void* const* d_in, const int* in_sizes, int n_in,
                              void* d_out, int out_size)
{
    const float* x   = (const float*)d_in[0];
    const float* seg = (const float*)d_in[1];
    const float* wgt = (const float*)d_in[2];
    float* out = (float*)d_out;

    cudaFuncSetAttribute(pconv_mma, cudaFuncAttributeMaxDynamicSharedMemorySize,
                         NSTAGE * STAGE);

    prep_all<<<3888, 256>>>(x, seg, wgt);

    dim3 grid(P / 128, 2);
    pconv_mma<<<grid, 256, NSTAGE * STAGE>>>(out);
}

// round 8
// speedup vs baseline: 11.7042x; 1.0162x over previous
#include <cuda_runtime.h>
#include <cuda_fp16.h>
#include <cstdint>

// ---------------------------------------------------------------- constants
#define HH 80
#define WW 80
#define CH 256
#define NC 22
#define DIM 256
#define P 25600              // 4*80*80 pixels
#define NCHUNK 36            // 9 taps * 4 chunks of 64 channels
// stage layout: A 16K | B 16K
#define STAGE 32768
#define NSTAGE 2

// device scratch
__device__ uint32_t g_selh2[P * 9];    // sel*norm as broadcast half2
__device__ uint4 g_w[144 * 512];       // weight fp16 smem-images (pre-swizzled 8KB blocks)
__device__ uint4 g_xf[4 * P * 8];      // x fp16, [ct][p][g] 16B groups

// ---------------------------------------------------------------- helpers
static __device__ __forceinline__ uint32_t smem_u32(const void* p) {
    uint32_t a;
    asm("{ .reg .u64 t; cvta.to.shared.u64 t, %1; cvt.u32.u64 %0, t; }" : "=r"(a) : "l"(p));
    return a;
}

#define LDSM4(r, addr) \
    asm volatile("ldmatrix.sync.aligned.m8n8.x4.shared.b16 {%0,%1,%2,%3},[%4];" \
        : "=r"((r)[0]), "=r"((r)[1]), "=r"((r)[2]), "=r"((r)[3]) : "r"(addr))
#define MMA(acc, a, b) \
    asm volatile("mma.sync.aligned.m16n8k16.row.col.f32.f16.f16.f32 " \
        "{%0,%1,%2,%3},{%4,%5,%6,%7},{%8,%9},{%0,%1,%2,%3};" \
        : "+f"((acc)[0]), "+f"((acc)[1]), "+f"((acc)[2]), "+f"((acc)[3]) \
        : "r"((a)[0]), "r"((a)[1]), "r"((a)[2]), "r"((a)[3]), "r"((b)[0]), "r"((b)[1]))
#define CPA(dst, src) \
    asm volatile("cp.async.cg.shared.global [%0], [%1], 16;" :: "r"(dst), "l"(src))

static __device__ __forceinline__ uint32_t hmul2u(uint32_t a, uint32_t s) {
    uint32_t r;
    asm("mul.rn.f16x2 %0, %1, %2;" : "=r"(r) : "r"(a), "r"(s));
    return r;
}

// ---------------------------------------------------------------- fused prep kernel
// blocks [0,400): selnorm (4 lanes/pixel) -> g_selh2
// blocks [400,3600): x -> fp16
// blocks [3600,3888): weight -> fp16 smem-image
__global__ void prep_all(const float* __restrict__ x,
                         const float* __restrict__ seg,
                         const float* __restrict__ wgt)
{
    int b = blockIdx.x;
    if (b < 400) {
        // ---- selnorm ----
        int gid = b * 256 + threadIdx.x;       // P*4 threads
        int p = gid >> 2, q = gid & 3;
        int w = p % WW, h = (p / WW) % HH;
        int c0 = q * 6;
        int ncl = (q == 3) ? 4 : 6;

        const float* cp_ = seg + (size_t)p * NC + c0;
        float cv[6];
#pragma unroll
        for (int i = 0; i < 6; i++) cv[i] = (i < ncl) ? cp_[i] : -1e30f;

        float m = cv[0];
#pragma unroll
        for (int i = 1; i < 6; i++) m = fmaxf(m, cv[i]);
        m = fmaxf(m, __shfl_xor_sync(0xffffffffu, m, 1));
        m = fmaxf(m, __shfl_xor_sync(0xffffffffu, m, 2));

        float sel[9];
        int cnt = 0;
#pragma unroll
        for (int k = 0; k < 9; k++) {
            int dh = k / 3 - 1, dw = k % 3 - 1;
            int hh = h + dh, ww = w + dw;
            float s = 0.0f;
            if (hh >= 0 && hh < HH && ww >= 0 && ww < WW) {
                const float* nb = seg + (size_t)(p + dh * WW + dw) * NC + c0;
#pragma unroll
                for (int i = 0; i < 6; i++)
                    if (i < ncl && cv[i] == m) s += nb[i];
            }
            s += __shfl_xor_sync(0xffffffffu, s, 1);
            s += __shfl_xor_sync(0xffffffffu, s, 2);
            sel[k] = s;
            if (s != 0.0f) cnt++;
        }
        float nrm = (cnt > 0) ? 9.0f / (float)cnt : 0.0f;
        for (int k = q; k < 9; k += 4) {
            __half hv = __float2half_rn(sel[k] * nrm);
            uint32_t u = (uint32_t)__half_as_ushort(hv);
            g_selh2[p * 9 + k] = u | (u << 16);
        }
    } else if (b < 3600) {
        // ---- x -> fp16 ----
        int gid = (b - 400) * 256 + threadIdx.x;   // P*32 threads
        int g8 = gid & 31;
        int p  = gid >> 5;
        int c0 = g8 * 8;
        int ct = c0 >> 6, g = (c0 >> 3) & 7;

        const float* src = x + (size_t)p * CH + c0;
        uint32_t h4[4];
#pragma unroll
        for (int j = 0; j < 4; j++) {
            __half h0 = __float2half_rn(src[2*j]);
            __half h1 = __float2half_rn(src[2*j+1]);
            h4[j] = (uint32_t)__half_as_ushort(h0) | ((uint32_t)__half_as_ushort(h1) << 16);
        }
        g_xf[(ct * P + p) * 8 + g] = make_uint4(h4[0], h4[1], h4[2], h4[3]);
    } else {
        // ---- weight -> fp16 pre-swizzled image ----
        int id = (b - 3600) * 256 + threadIdx.x;   // 73728 threads
        int cc8  = id & 7;
        int row  = (id >> 3) & 63;
        int blk  = id >> 9;            // 0..143
        int nb4  = blk & 3;
        int chunk = blk >> 2;
        int ktap = chunk >> 2, ct = chunk & 3;
        int d  = nb4 * 64 + row;
        int c0 = ct * 64 + cc8 * 8;

        uint32_t h4[4];
#pragma unroll
        for (int j = 0; j < 4; j++) {
            float v0 = wgt[(size_t)(c0 + 2*j)     * (9 * DIM) + ktap * DIM + d];
            float v1 = wgt[(size_t)(c0 + 2*j + 1) * (9 * DIM) + ktap * DIM + d];
            __half h0 = __float2half_rn(v0);
            __half h1 = __float2half_rn(v1);
            h4[j] = (uint32_t)__half_as_ushort(h0) | ((uint32_t)__half_as_ushort(h1) << 16);
        }
        int idx = blk * 512 + row * 8 + (cc8 ^ (row & 7));
        g_w[idx] = make_uint4(h4[0], h4[1], h4[2], h4[3]);
    }
}

// ---------------------------------------------------------------- HMMA implicit GEMM
// CTA 128(M) x 128(N), 256 threads, 8 warps (4M x 2N), warp tile 32x64.
// sel folded at A-fill time (LDG -> HMUL2 -> swizzled STS); inner loop is
// pure ldmatrix + MMA. B via cp.async. 2-stage pipeline, 2 CTAs/SM.
__global__ __launch_bounds__(256, 2) void pconv_mma(float* __restrict__ out)
{
    extern __shared__ __align__(1024) char smem[];
    const uint32_t sb = smem_u32(smem);
    const int tid = threadIdx.x, wid = tid >> 5, lid = tid & 31;
    const int p0 = blockIdx.x * 128;
    const int nblk = blockIdx.y;            // 0..1 (128-wide N block)
    const int wm = wid & 3, wn = wid >> 2;  // 4 M-quarters x 2 N-halves(64)

    // ldmatrix lane addressing
    const int arow = wm * 32 + (lid & 15);
    const int achp = lid >> 4;
    const int bi = lid >> 3;                   // 0..3
    const int bnt = bi >> 1, bkh = bi & 1;
    const int brow = wn * 64 + bnt * 8 + (lid & 7);
    const int bsw  = lid & 7;

    float acc[2][8][4];
#pragma unroll
    for (int i = 0; i < 2; i++)
#pragma unroll
        for (int j = 0; j < 8; j++)
#pragma unroll
            for (int r = 0; r < 4; r++) acc[i][j][r] = 0.0f;

    // A prefetch registers (one chunk ahead)
    uint4 aR[4];
    uint32_t sR[4];

    auto ldgA = [&](int chunk) {
        int ktap = chunk >> 2, ct = chunk & 3;
        int delta = (ktap / 3 - 1) * WW + (ktap % 3 - 1);
#pragma unroll
        for (int i = 0; i < 4; i++) {
            int u = tid + i * 256;
            int fr = u >> 3, fg = u & 7;
            int nb = p0 + fr + delta; nb = nb < 0 ? 0 : (nb >= P ? P - 1 : nb);
            aR[i] = g_xf[(ct * P + nb) * 8 + (fg ^ (nb & 7))];
            sR[i] = g_selh2[(p0 + fr) * 9 + ktap];
        }
    };
    auto stsA = [&](int s) {
        char* st = smem + s * STAGE;
#pragma unroll
        for (int i = 0; i < 4; i++) {
            int u = tid + i * 256;
            int fr = u >> 3, fg = u & 7;
            uint4 v = aR[i];
            v.x = hmul2u(v.x, sR[i]);
            v.y = hmul2u(v.y, sR[i]);
            v.z = hmul2u(v.z, sR[i]);
            v.w = hmul2u(v.w, sR[i]);
            *(uint4*)(st + fr * 128 + fg * 16) = v;
        }
    };
    auto cpB = [&](int chunk, int s) {
        uint32_t st = sb + s * STAGE;
        const uint4* wp = g_w + (size_t)(chunk * 4 + nblk * 2) * 512;
#pragma unroll
        for (int i = 0; i < 4; i++)
            CPA(st + 16384 + (tid + i * 256) * 16, wp + tid + i * 256);
        asm volatile("cp.async.commit_group;" ::: "memory");
    };

    auto compute = [&](int chunk, int s) {
        uint32_t st = sb + s * STAGE;
        int ktap = chunk >> 2;
        int delta = (ktap / 3 - 1) * WW + (ktap % 3 - 1);
        int asw = (arow + delta + 128) & 7;       // tap-shifted swizzle phase
        uint32_t Ap = st, Bp = st + 16384;
#pragma unroll
        for (int ks = 0; ks < 4; ks++) {
            uint32_t a[2][4], bfr[8][2];
#pragma unroll
            for (int mt = 0; mt < 2; mt++) {
                uint32_t off = (uint32_t)(arow + mt * 16) * 128
                             + (((ks * 2 + achp) ^ asw) << 4);
                LDSM4(a[mt], Ap + off);
            }
#pragma unroll
            for (int ntp = 0; ntp < 4; ntp++) {
                uint32_t off = (uint32_t)(brow + ntp * 16) * 128
                             + (((ks * 2 + bkh) ^ bsw) << 4);
                uint32_t r[4];
                LDSM4(r, Bp + off);
                bfr[ntp*2+0][0] = r[0]; bfr[ntp*2+0][1] = r[1];
                bfr[ntp*2+1][0] = r[2]; bfr[ntp*2+1][1] = r[3];
            }
#pragma unroll
            for (int mt = 0; mt < 2; mt++)
#pragma unroll
                for (int nt = 0; nt < 8; nt++)
                    MMA(acc[mt][nt], a[mt], bfr[nt]);
        }
    };

    // prologue: stage 0 filled, A(1) in regs
    ldgA(0);
    stsA(0);
    cpB(0, 0);
    ldgA(1);
    asm volatile("cp.async.wait_group 0;" ::: "memory");
    __syncthreads();

#pragma unroll 1
    for (int c = 0; c < NCHUNK; c++) {
        int s = c & 1;
        if (c + 1 < NCHUNK) cpB(c + 1, s ^ 1);     // B async into other stage
        compute(c, s);
        if (c + 1 < NCHUNK) {
            stsA(s ^ 1);                           // sel-folded A for c+1
            if (c + 2 < NCHUNK) ldgA(c + 2);       // prefetch next A into regs
            asm volatile("cp.async.wait_group 0;" ::: "memory");
        }
        __syncthreads();
    }

    // epilogue
#pragma unroll
    for (int mt = 0; mt < 2; mt++) {
        int r0 = p0 + wm * 32 + mt * 16 + (lid >> 2);
#pragma unroll
        for (int nt = 0; nt < 8; nt++) {
            int col = nblk * 128 + wn * 64 + nt * 8 + (lid & 3) * 2;
            float2* d0 = (float2*)(out + (size_t)r0 * DIM + col);
            float2* d1 = (float2*)(out + (size_t)(r0 + 8) * DIM + col);
            *d0 = make_float2(acc[mt][nt][0], acc[mt][nt][1]);
            *d1 = make_float2(acc[mt][nt][2], acc[mt][nt][3]);
        }
    }
}

// ---------------------------------------------------------------- launch
extern "C" void kernel_launch(void* const* d_in, const int* in_sizes, int n_in,
                              void* d_out, int out_size)
{
    const float* x   = (const float*)d_in[0];
    const float* seg = (const float*)d_in[1];
    const float* wgt = (const float*)d_in[2];
    float* out = (float*)d_out;

    cudaFuncSetAttribute(pconv_mma, cudaFuncAttributeMaxDynamicSharedMemorySize,
                         NSTAGE * STAGE);

    prep_all<<<3888, 256>>>(x, seg, wgt);

    dim3 grid(P / 128, 2);
    pconv_mma<<<grid, 256, NSTAGE * STAGE>>>(out);
}